// round 16
// baseline (speedup 1.0000x reference)
#include <cuda_runtime.h>
#include <float.h>
#include <math.h>

#define BB   8
#define NN   4096
#define SS   1024
#define NSMP 32
#define CIN  64
#define CMLP 128
#define COUT 256

// ---------------- scratch (device globals; no runtime allocation) ----------
__device__ int   g_fps [BB*SS];
__device__ int   g_gidx[BB*SS*NSMP];
__device__ int   g_cnt [BB*NN];
__device__ float g_W   [CIN*COUT];
__device__ float g_bvec[COUT];
__device__ float g_h   [BB*NN*COUT];          // 33.5 MB, fits L2
__device__ float g_part[256*COUT*2];
__device__ float g_mean[COUT];
__device__ float g_istd[COUT];

// ---------------- packed f32x2 helpers (per-lane .rn => bit-exact) ---------
typedef unsigned long long u64;
__device__ __forceinline__ u64 f2pack(float a, float b) {
    u64 r; asm("mov.b64 %0, {%1, %2};" : "=l"(r) : "f"(a), "f"(b)); return r;
}
__device__ __forceinline__ void f2unpack(u64 v, float& a, float& b) {
    asm("mov.b64 {%0, %1}, %2;" : "=f"(a), "=f"(b) : "l"(v));
}
__device__ __forceinline__ u64 padd(u64 a, u64 b) {
    u64 r; asm("add.rn.f32x2 %0, %1, %2;" : "=l"(r) : "l"(a), "l"(b)); return r;
}
__device__ __forceinline__ u64 pmul(u64 a, u64 b) {
    u64 r; asm("mul.rn.f32x2 %0, %1, %2;" : "=l"(r) : "l"(a), "l"(b)); return r;
}

// exact (non-FMA) squared distance, matching XLA ((dx^2+dy^2)+dz^2)
__device__ __forceinline__ float dist3(float x, float y, float z,
                                       float cx, float cy, float cz) {
    float dx = __fsub_rn(x, cx);
    float dy = __fsub_rn(y, cy);
    float dz = __fsub_rn(z, cz);
    return __fadd_rn(__fadd_rn(__fmul_rn(dx, dx), __fmul_rn(dy, dy)),
                     __fmul_rn(dz, dz));
}

// ---------------- 1) farthest point sampling: one block per batch ----------
// 128 threads, 32 points each (16 packed pairs). One __syncthreads per iter.
// Argmax merge tree compares float BITS as u32 (valid: all distances >= +0,
// so uint order == float order) -> ISETP on the ALU pipe, freeing the FMA
// pipe for the packed distance math.
__global__ __launch_bounds__(128, 1)
void fps_kernel(const float* __restrict__ xyz) {
    extern __shared__ u64 sm64[];
    u64* snx = sm64;
    u64* sny = sm64 + NN;
    u64* snz = sm64 + 2 * NN;
    __shared__ alignas(32) u64 skey[2][4];

    const int b    = blockIdx.x;
    const int tid  = threadIdx.x;
    const int lane = tid & 31, wid = tid >> 5;

    const float* base = xyz + (size_t)b * NN * 3;

    u64 px2[16], py2[16], pz2[16];
    float dmin[32];
#pragma unroll
    for (int j = 0; j < 16; ++j) {
        int p = tid * 32 + 2 * j;
        float x0 = base[3 * p + 0], y0 = base[3 * p + 1], z0 = base[3 * p + 2];
        float x1 = base[3 * p + 3], y1 = base[3 * p + 4], z1 = base[3 * p + 5];
        px2[j] = f2pack(x0, x1);
        py2[j] = f2pack(y0, y1);
        pz2[j] = f2pack(z0, z1);
        snx[p]     = f2pack(-x0, -x0);
        snx[p + 1] = f2pack(-x1, -x1);
        sny[p]     = f2pack(-y0, -y0);
        sny[p + 1] = f2pack(-y1, -y1);
        snz[p]     = f2pack(-z0, -z0);
        snz[p + 1] = f2pack(-z1, -z1);
        dmin[2 * j] = 1e10f; dmin[2 * j + 1] = 1e10f;
    }
    __syncthreads();

    int far = 0;
    for (int it = 0; it < SS; ++it) {
        if (tid == 0) g_fps[b * SS + it] = far;
        const u64 ncx = snx[far];
        const u64 ncy = sny[far];
        const u64 ncz = snz[far];

#pragma unroll
        for (int j = 0; j < 16; ++j) {
            u64 dx2 = padd(px2[j], ncx);   // x - cx  (exact: x + (-cx))
            u64 dy2 = padd(py2[j], ncy);
            u64 dz2 = padd(pz2[j], ncz);
            u64 s   = padd(padd(pmul(dx2, dx2), pmul(dy2, dy2)),
                           pmul(dz2, dz2));
            float d0, d1;
            f2unpack(s, d0, d1);
            dmin[2 * j]     = fminf(dmin[2 * j],     d0);
            dmin[2 * j + 1] = fminf(dmin[2 * j + 1], d1);
        }

        // order-preserving argmax merge tree on float BITS (u32 compares,
        // ALU pipe). '>=' keeps left = lowest index. Valid since all
        // dmin >= +0 (uint order == float order; no -0 possible).
        unsigned mu[16]; int mi[16];
#pragma unroll
        for (int k = 0; k < 16; ++k) {
            unsigned a  = __float_as_uint(dmin[2 * k]);
            unsigned b2 = __float_as_uint(dmin[2 * k + 1]);
            bool c = a >= b2;
            mu[k] = c ? a : b2;
            mi[k] = c ? 2 * k : 2 * k + 1;
        }
#pragma unroll
        for (int k = 0; k < 8; ++k) {
            bool c = mu[2 * k] >= mu[2 * k + 1];
            mu[k] = c ? mu[2 * k] : mu[2 * k + 1];
            mi[k] = c ? mi[2 * k] : mi[2 * k + 1];
        }
#pragma unroll
        for (int k = 0; k < 4; ++k) {
            bool c = mu[2 * k] >= mu[2 * k + 1];
            mu[k] = c ? mu[2 * k] : mu[2 * k + 1];
            mi[k] = c ? mi[2 * k] : mi[2 * k + 1];
        }
        {
            bool c0 = mu[0] >= mu[1];
            unsigned a0 = c0 ? mu[0] : mu[1]; int b0 = c0 ? mi[0] : mi[1];
            bool c1 = mu[2] >= mu[3];
            unsigned a1 = c1 ? mu[2] : mu[3]; int b1 = c1 ? mi[2] : mi[3];
            bool c  = a0 >= a1;
            mu[0] = c ? a0 : a1; mi[0] = c ? b0 : b1;
        }
        const unsigned vb = mu[0];
        const int      bi = tid * 32 + mi[0];

        // warp argmax: REDUX max value, then REDUX min index among winners
        unsigned wmax = __reduce_max_sync(0xffffffffu, vb);
        unsigned ikey = (vb == wmax) ? (unsigned)bi : 0xffffffffu;
        unsigned wbi  = __reduce_min_sync(0xffffffffu, ikey);

        const int buf = it & 1;
        if (lane == 0)
            skey[buf][wid] = ((u64)wmax << 32) | (u64)(4095u - wbi);
        __syncthreads();

        // block argmax: 4 packed slots, plain u64 max (keys unique)
        {
            ulonglong2 s01 = *(const ulonglong2*)&skey[buf][0];
            ulonglong2 s23 = *(const ulonglong2*)&skey[buf][2];
            u64 m0 = (s01.x >= s01.y) ? s01.x : s01.y;
            u64 m1 = (s23.x >= s23.y) ? s23.x : s23.y;
            u64 m  = (m0 >= m1) ? m0 : m1;
            far = 4095 - (int)((unsigned)m & 0xFFFu);
        }
    }
}

// ---------------- 2) fused weights W = W1@Wc, bvec = b1@Wc + bc; zero counts
__global__ __launch_bounds__(256)
void wfuse_kernel(const float* __restrict__ W1, const float* __restrict__ b1,
                  const float* __restrict__ Wc, const float* __restrict__ bc) {
    const int r = blockIdx.x;   // 0..63
    const int c = threadIdx.x;  // 0..255
    float acc = 0.f;
#pragma unroll 8
    for (int k = 0; k < CMLP; ++k)
        acc = fmaf(W1[r * CMLP + k], Wc[k * COUT + c], acc);
    g_W[r * COUT + c] = acc;
    if (r == 0) {
        float a = 0.f;
#pragma unroll 8
        for (int k = 0; k < CMLP; ++k)
            a = fmaf(b1[k], Wc[k * COUT + c], a);
        g_bvec[c] = a + bc[c];
    }
    // zero counts: 64 blocks x 512 entries
    g_cnt[r * 512 + c]       = 0;
    g_cnt[r * 512 + 256 + c] = 0;
}

// ---------------- 3) ball query: ONE centroid per warp, float4 smem -------
// 512 threads = 16 warps/block, 16 centroids/block; grid (SS/16, BB).
__global__ __launch_bounds__(512, 1)
void ballq_kernel(const float* __restrict__ xyz) {
    extern __shared__ float4 sp[];   // NN float4 = 64 KB
    __shared__ int wbuf[16][NSMP];

    const int b = blockIdx.y;
    const int tid = threadIdx.x, lane = tid & 31, wid = tid >> 5;

    const float* base = xyz + (size_t)b * NN * 3;
    for (int i = tid; i < NN; i += 512)
        sp[i] = make_float4(base[3 * i + 0], base[3 * i + 1],
                            base[3 * i + 2], 0.f);
    __syncthreads();

    const float R2 = (float)(0.15 * 0.15);  // match JAX f64->f32 cast

    const int s   = blockIdx.x * 16 + wid;
    const int far = g_fps[b * SS + s];
    const float4 cc = sp[far];

    int cnt = 0;
    for (int bp = 0; bp < NN; bp += 32) {
        int p = bp + lane;
        float4 q = sp[p];
        float d = dist3(q.x, q.y, q.z, cc.x, cc.y, cc.z);
        bool in = (d <= R2);
        unsigned m = __ballot_sync(0xffffffffu, in);
        int off = __popc(m & ((1u << lane) - 1u));
        if (in && cnt + off < NSMP) wbuf[wid][cnt + off] = p;
        cnt += __popc(m);
        if (cnt >= NSMP) { cnt = NSMP; break; }
    }
    __syncwarp();
    int v = (lane < cnt) ? wbuf[wid][lane] : wbuf[wid][0];
    g_gidx[((size_t)b * SS + s) * NSMP + lane] = v;
    atomicAdd(&g_cnt[b * NN + v], 1);
}

// ---------------- 4) h = points @ W + bvec  -------------------------------
// 128 threads/block, 32 rows/block, 2 channels per thread (w2 in registers).
__global__ __launch_bounds__(128, 2)
void hfull_kernel(const float* __restrict__ points) {
    __shared__ float psh[32 * CIN];  // 32 rows x 64 cols = 8 KB
    const int rowBase = blockIdx.x * 32;
    const int tid = threadIdx.x;

    {   // vectorized tile load: 512 float4, 128 threads -> 4 each
        const float4* src = (const float4*)(points + (size_t)rowBase * CIN);
        float4* dst = (float4*)psh;
#pragma unroll
        for (int i = 0; i < 4; ++i) dst[tid + 128 * i] = src[tid + 128 * i];
    }
    __syncthreads();

    const int c = tid * 2;  // channel pair (c, c+1)
    float2 w2[CIN];
#pragma unroll
    for (int k = 0; k < CIN; ++k)
        w2[k] = *(const float2*)&g_W[k * COUT + c];
    const float2 bv2 = *(const float2*)&g_bvec[c];

    for (int r0 = 0; r0 < 32; r0 += 4) {
        float a0x = bv2.x, a0y = bv2.y, a1x = bv2.x, a1y = bv2.y;
        float a2x = bv2.x, a2y = bv2.y, a3x = bv2.x, a3y = bv2.y;
        const float4* p0 = (const float4*)&psh[(r0 + 0) * CIN];
        const float4* p1 = (const float4*)&psh[(r0 + 1) * CIN];
        const float4* p2 = (const float4*)&psh[(r0 + 2) * CIN];
        const float4* p3 = (const float4*)&psh[(r0 + 3) * CIN];
#pragma unroll
        for (int k4 = 0; k4 < CIN / 4; ++k4) {
            float4 v0 = p0[k4], v1 = p1[k4], v2 = p2[k4], v3 = p3[k4];
            float2 u0 = w2[4 * k4], u1 = w2[4 * k4 + 1],
                   u2 = w2[4 * k4 + 2], u3 = w2[4 * k4 + 3];
            a0x = fmaf(v0.x, u0.x, a0x); a0y = fmaf(v0.x, u0.y, a0y);
            a0x = fmaf(v0.y, u1.x, a0x); a0y = fmaf(v0.y, u1.y, a0y);
            a0x = fmaf(v0.z, u2.x, a0x); a0y = fmaf(v0.z, u2.y, a0y);
            a0x = fmaf(v0.w, u3.x, a0x); a0y = fmaf(v0.w, u3.y, a0y);
            a1x = fmaf(v1.x, u0.x, a1x); a1y = fmaf(v1.x, u0.y, a1y);
            a1x = fmaf(v1.y, u1.x, a1x); a1y = fmaf(v1.y, u1.y, a1y);
            a1x = fmaf(v1.z, u2.x, a1x); a1y = fmaf(v1.z, u2.y, a1y);
            a1x = fmaf(v1.w, u3.x, a1x); a1y = fmaf(v1.w, u3.y, a1y);
            a2x = fmaf(v2.x, u0.x, a2x); a2y = fmaf(v2.x, u0.y, a2y);
            a2x = fmaf(v2.y, u1.x, a2x); a2y = fmaf(v2.y, u1.y, a2y);
            a2x = fmaf(v2.z, u2.x, a2x); a2y = fmaf(v2.z, u2.y, a2y);
            a2x = fmaf(v2.w, u3.x, a2x); a2y = fmaf(v2.w, u3.y, a2y);
            a3x = fmaf(v3.x, u0.x, a3x); a3y = fmaf(v3.x, u0.y, a3y);
            a3x = fmaf(v3.y, u1.x, a3x); a3y = fmaf(v3.y, u1.y, a3y);
            a3x = fmaf(v3.z, u2.x, a3x); a3y = fmaf(v3.z, u2.y, a3y);
            a3x = fmaf(v3.w, u3.x, a3x); a3y = fmaf(v3.w, u3.y, a3y);
        }
        *(float2*)&g_h[(size_t)(rowBase + r0 + 0) * COUT + c] = make_float2(a0x, a0y);
        *(float2*)&g_h[(size_t)(rowBase + r0 + 1) * COUT + c] = make_float2(a1x, a1y);
        *(float2*)&g_h[(size_t)(rowBase + r0 + 2) * COUT + c] = make_float2(a2x, a2y);
        *(float2*)&g_h[(size_t)(rowBase + r0 + 3) * COUT + c] = make_float2(a3x, a3y);
    }
}

// ---------------- 5) BN stats: count-weighted sum / sumsq per channel -----
__global__ __launch_bounds__(256)
void stats1_kernel() {
    const int c  = threadIdx.x;
    const int r0 = blockIdx.x * 128;
    float s = 0.f, q = 0.f;
    for (int r = r0; r < r0 + 128; ++r) {
        int w = g_cnt[r];
        if (w) {
            float v  = g_h[(size_t)r * COUT + c];
            float wv = (float)w * v;
            s += wv;
            q = fmaf(wv, v, q);
        }
    }
    g_part[((size_t)blockIdx.x * COUT + c) * 2 + 0] = s;
    g_part[((size_t)blockIdx.x * COUT + c) * 2 + 1] = q;
}

__global__ __launch_bounds__(256)
void stats2_kernel() {
    const int c = threadIdx.x;
    float s = 0.f, q = 0.f;
    for (int j = 0; j < 256; ++j) {
        s += g_part[((size_t)j * COUT + c) * 2 + 0];
        q += g_part[((size_t)j * COUT + c) * 2 + 1];
    }
    const float M = (float)(BB * SS * NSMP);  // 262144
    float mean = s / M;
    float var  = q / M - mean * mean;
    g_mean[c] = mean;
    g_istd[c] = 1.0f / sqrtf(var + 1e-5f);
}

// ---------------- 6) gather + max/min + BN-affine + relu ------------------
__global__ __launch_bounds__(128)
void final_kernel(const float* __restrict__ gamma,
                  const float* __restrict__ beta,
                  float* __restrict__ out) {
    const int sgl = blockIdx.x;      // 0..8191
    const int b   = sgl >> 10;
    const int t   = threadIdx.x;     // 0..127
    const int c   = t * 2;

    __shared__ int idxs[NSMP];
    if (t < NSMP) idxs[t] = g_gidx[(size_t)sgl * NSMP + t];
    __syncthreads();

    const float* hb = g_h + (size_t)b * NN * COUT + c;
    float vmaxx = -FLT_MAX, vmaxy = -FLT_MAX;
    float vminx =  FLT_MAX, vminy =  FLT_MAX;
#pragma unroll
    for (int n = 0; n < NSMP; ++n) {
        float2 v = *(const float2*)(hb + (size_t)idxs[n] * COUT);
        vmaxx = fmaxf(vmaxx, v.x); vmaxy = fmaxf(vmaxy, v.y);
        vminx = fminf(vminx, v.x); vminy = fminf(vminy, v.y);
    }
    float2 g = *(const float2*)&gamma[c];
    float2 be = *(const float2*)&beta[c];
    float2 is = *(const float2*)&g_istd[c];
    float2 mn = *(const float2*)&g_mean[c];
    float ax = g.x * is.x, ay = g.y * is.y;
    float bx = fmaf(-ax, mn.x, be.x), by = fmaf(-ay, mn.y, be.y);
    float vx = (ax >= 0.f) ? vmaxx : vminx;
    float vy = (ay >= 0.f) ? vmaxy : vminy;
    float2 o;
    o.x = fmaxf(0.f, fmaf(ax, vx, bx));
    o.y = fmaxf(0.f, fmaf(ay, vy, by));
    *(float2*)&out[(size_t)sgl * COUT + c] = o;
}

// ---------------- launch: forked-stream graph ------------------------------
// default stream: fps -> (wait wfuse) ballq -> (wait hfull) stats1/2 -> final
// side stream   : wfuse -> hfull            (overlaps fps)
extern "C" void kernel_launch(void* const* d_in, const int* in_sizes, int n_in,
                              void* d_out, int out_size) {
    const float* xyz    = (const float*)d_in[0];
    // d_in[1] = t, unused by the reference
    const float* points = (const float*)d_in[2];
    const float* W1     = (const float*)d_in[3];
    const float* b1     = (const float*)d_in[4];
    const float* Wc     = (const float*)d_in[5];
    const float* bc     = (const float*)d_in[6];
    const float* gamma  = (const float*)d_in[7];
    const float* beta   = (const float*)d_in[8];
    float* out = (float*)d_out;

    const size_t smemFPS = 3 * NN * sizeof(u64);     // 98304 B dynamic
    const size_t smemBQ  = NN * sizeof(float4);      // 65536 B dynamic

    cudaFuncSetAttribute(fps_kernel,
                         cudaFuncAttributeMaxDynamicSharedMemorySize, 131072);
    cudaFuncSetAttribute(ballq_kernel,
                         cudaFuncAttributeMaxDynamicSharedMemorySize, 98304);

    cudaStream_t s2;
    cudaStreamCreateWithFlags(&s2, cudaStreamNonBlocking);
    cudaEvent_t e0, ewf, ehf;
    cudaEventCreateWithFlags(&e0,  cudaEventDisableTiming);
    cudaEventCreateWithFlags(&ewf, cudaEventDisableTiming);
    cudaEventCreateWithFlags(&ehf, cudaEventDisableTiming);

    // fork side stream off the (possibly capturing) default stream
    cudaEventRecord(e0, 0);
    cudaStreamWaitEvent(s2, e0, 0);

    fps_kernel  <<<BB, 128, smemFPS, 0>>>(xyz);

    wfuse_kernel<<<64, 256, 0, s2>>>(W1, b1, Wc, bc);
    cudaEventRecord(ewf, s2);
    hfull_kernel<<<(BB * NN) / 32, 128, 0, s2>>>(points);
    cudaEventRecord(ehf, s2);

    cudaStreamWaitEvent(0, ewf, 0);   // ballq needs g_cnt zeroed (wfuse)
    ballq_kernel<<<dim3(SS / 16, BB), 512, smemBQ, 0>>>(xyz);

    cudaStreamWaitEvent(0, ehf, 0);   // join side stream: stats need g_h
    stats1_kernel<<<256, 256, 0, 0>>>();
    stats2_kernel<<<1, 256, 0, 0>>>();
    final_kernel<<<BB * SS, 128, 0, 0>>>(gamma, beta, out);
    // handles intentionally leaked: capture may still be in progress and
    // kernel_launch is invoked only a few times outside graph replay.
}

// round 17
// speedup vs baseline: 1.0489x; 1.0489x over previous
#include <cuda_runtime.h>
#include <float.h>
#include <math.h>

#define BB   8
#define NN   4096
#define SS   1024
#define NSMP 32
#define CIN  64
#define CMLP 128
#define COUT 256

// ---------------- scratch (device globals; no runtime allocation) ----------
__device__ int   g_fps [BB*SS];
__device__ int   g_gidx[BB*SS*NSMP];
__device__ int   g_cnt [BB*NN];
__device__ float g_W   [CIN*COUT];
__device__ float g_bvec[COUT];
__device__ float g_h   [BB*NN*COUT];          // 33.5 MB, fits L2
__device__ float g_part[256*COUT*2];
__device__ float g_mean[COUT];
__device__ float g_istd[COUT];

// ---------------- packed f32x2 helpers (per-lane .rn => bit-exact) ---------
typedef unsigned long long u64;
__device__ __forceinline__ u64 f2pack(float a, float b) {
    u64 r; asm("mov.b64 %0, {%1, %2};" : "=l"(r) : "f"(a), "f"(b)); return r;
}
__device__ __forceinline__ void f2unpack(u64 v, float& a, float& b) {
    asm("mov.b64 {%0, %1}, %2;" : "=f"(a), "=f"(b) : "l"(v));
}
__device__ __forceinline__ u64 padd(u64 a, u64 b) {
    u64 r; asm("add.rn.f32x2 %0, %1, %2;" : "=l"(r) : "l"(a), "l"(b)); return r;
}
__device__ __forceinline__ u64 pmul(u64 a, u64 b) {
    u64 r; asm("mul.rn.f32x2 %0, %1, %2;" : "=l"(r) : "l"(a), "l"(b)); return r;
}

// exact (non-FMA) squared distance, matching XLA ((dx^2+dy^2)+dz^2)
__device__ __forceinline__ float dist3(float x, float y, float z,
                                       float cx, float cy, float cz) {
    float dx = __fsub_rn(x, cx);
    float dy = __fsub_rn(y, cy);
    float dz = __fsub_rn(z, cz);
    return __fadd_rn(__fadd_rn(__fmul_rn(dx, dx), __fmul_rn(dy, dy)),
                     __fmul_rn(dz, dz));
}

// ---------------- 1) farthest point sampling: one block per batch ----------
// 128 threads, 32 points each (16 packed pairs). One __syncthreads per iter.
// Argmax merge tree compares float BITS as u32 (valid: all distances >= +0,
// so uint order == float order) -> ISETP on the ALU pipe, freeing the FMA
// pipe for the packed distance math.
__global__ __launch_bounds__(128, 1)
void fps_kernel(const float* __restrict__ xyz) {
    extern __shared__ u64 sm64[];
    u64* snx = sm64;
    u64* sny = sm64 + NN;
    u64* snz = sm64 + 2 * NN;
    __shared__ alignas(32) u64 skey[2][4];

    const int b    = blockIdx.x;
    const int tid  = threadIdx.x;
    const int lane = tid & 31, wid = tid >> 5;

    const float* base = xyz + (size_t)b * NN * 3;

    u64 px2[16], py2[16], pz2[16];
    float dmin[32];
#pragma unroll
    for (int j = 0; j < 16; ++j) {
        int p = tid * 32 + 2 * j;
        float x0 = base[3 * p + 0], y0 = base[3 * p + 1], z0 = base[3 * p + 2];
        float x1 = base[3 * p + 3], y1 = base[3 * p + 4], z1 = base[3 * p + 5];
        px2[j] = f2pack(x0, x1);
        py2[j] = f2pack(y0, y1);
        pz2[j] = f2pack(z0, z1);
        snx[p]     = f2pack(-x0, -x0);
        snx[p + 1] = f2pack(-x1, -x1);
        sny[p]     = f2pack(-y0, -y0);
        sny[p + 1] = f2pack(-y1, -y1);
        snz[p]     = f2pack(-z0, -z0);
        snz[p + 1] = f2pack(-z1, -z1);
        dmin[2 * j] = 1e10f; dmin[2 * j + 1] = 1e10f;
    }
    __syncthreads();

    int far = 0;
    for (int it = 0; it < SS; ++it) {
        if (tid == 0) g_fps[b * SS + it] = far;
        const u64 ncx = snx[far];
        const u64 ncy = sny[far];
        const u64 ncz = snz[far];

#pragma unroll
        for (int j = 0; j < 16; ++j) {
            u64 dx2 = padd(px2[j], ncx);   // x - cx  (exact: x + (-cx))
            u64 dy2 = padd(py2[j], ncy);
            u64 dz2 = padd(pz2[j], ncz);
            u64 s   = padd(padd(pmul(dx2, dx2), pmul(dy2, dy2)),
                           pmul(dz2, dz2));
            float d0, d1;
            f2unpack(s, d0, d1);
            dmin[2 * j]     = fminf(dmin[2 * j],     d0);
            dmin[2 * j + 1] = fminf(dmin[2 * j + 1], d1);
        }

        // order-preserving argmax merge tree on float BITS (u32 compares,
        // ALU pipe). '>=' keeps left = lowest index. Valid since all
        // dmin >= +0 (uint order == float order; no -0 possible).
        unsigned mu[16]; int mi[16];
#pragma unroll
        for (int k = 0; k < 16; ++k) {
            unsigned a  = __float_as_uint(dmin[2 * k]);
            unsigned b2 = __float_as_uint(dmin[2 * k + 1]);
            bool c = a >= b2;
            mu[k] = c ? a : b2;
            mi[k] = c ? 2 * k : 2 * k + 1;
        }
#pragma unroll
        for (int k = 0; k < 8; ++k) {
            bool c = mu[2 * k] >= mu[2 * k + 1];
            mu[k] = c ? mu[2 * k] : mu[2 * k + 1];
            mi[k] = c ? mi[2 * k] : mi[2 * k + 1];
        }
#pragma unroll
        for (int k = 0; k < 4; ++k) {
            bool c = mu[2 * k] >= mu[2 * k + 1];
            mu[k] = c ? mu[2 * k] : mu[2 * k + 1];
            mi[k] = c ? mi[2 * k] : mi[2 * k + 1];
        }
        {
            bool c0 = mu[0] >= mu[1];
            unsigned a0 = c0 ? mu[0] : mu[1]; int b0 = c0 ? mi[0] : mi[1];
            bool c1 = mu[2] >= mu[3];
            unsigned a1 = c1 ? mu[2] : mu[3]; int b1 = c1 ? mi[2] : mi[3];
            bool c  = a0 >= a1;
            mu[0] = c ? a0 : a1; mi[0] = c ? b0 : b1;
        }
        const unsigned vb = mu[0];
        const int      bi = tid * 32 + mi[0];

        // warp argmax: REDUX max value, then REDUX min index among winners
        unsigned wmax = __reduce_max_sync(0xffffffffu, vb);
        unsigned ikey = (vb == wmax) ? (unsigned)bi : 0xffffffffu;
        unsigned wbi  = __reduce_min_sync(0xffffffffu, ikey);

        const int buf = it & 1;
        if (lane == 0)
            skey[buf][wid] = ((u64)wmax << 32) | (u64)(4095u - wbi);
        __syncthreads();

        // block argmax: 4 packed slots, plain u64 max (keys unique)
        {
            ulonglong2 s01 = *(const ulonglong2*)&skey[buf][0];
            ulonglong2 s23 = *(const ulonglong2*)&skey[buf][2];
            u64 m0 = (s01.x >= s01.y) ? s01.x : s01.y;
            u64 m1 = (s23.x >= s23.y) ? s23.x : s23.y;
            u64 m  = (m0 >= m1) ? m0 : m1;
            far = 4095 - (int)((unsigned)m & 0xFFFu);
        }
    }
}

// ---------------- 2) fused weights W = W1@Wc, bvec = b1@Wc + bc; zero counts
__global__ __launch_bounds__(256)
void wfuse_kernel(const float* __restrict__ W1, const float* __restrict__ b1,
                  const float* __restrict__ Wc, const float* __restrict__ bc) {
    const int r = blockIdx.x;   // 0..63
    const int c = threadIdx.x;  // 0..255
    float acc = 0.f;
#pragma unroll 8
    for (int k = 0; k < CMLP; ++k)
        acc = fmaf(W1[r * CMLP + k], Wc[k * COUT + c], acc);
    g_W[r * COUT + c] = acc;
    if (r == 0) {
        float a = 0.f;
#pragma unroll 8
        for (int k = 0; k < CMLP; ++k)
            a = fmaf(b1[k], Wc[k * COUT + c], a);
        g_bvec[c] = a + bc[c];
    }
    // zero counts: 64 blocks x 512 entries
    g_cnt[r * 512 + c]       = 0;
    g_cnt[r * 512 + 256 + c] = 0;
}

// ---------------- 3) ball query: ONE centroid per warp, float4 smem -------
// 512 threads = 16 warps/block, 16 centroids/block; grid (SS/16, BB).
__global__ __launch_bounds__(512, 1)
void ballq_kernel(const float* __restrict__ xyz) {
    extern __shared__ float4 sp[];   // NN float4 = 64 KB
    __shared__ int wbuf[16][NSMP];

    const int b = blockIdx.y;
    const int tid = threadIdx.x, lane = tid & 31, wid = tid >> 5;

    const float* base = xyz + (size_t)b * NN * 3;
    for (int i = tid; i < NN; i += 512)
        sp[i] = make_float4(base[3 * i + 0], base[3 * i + 1],
                            base[3 * i + 2], 0.f);
    __syncthreads();

    const float R2 = (float)(0.15 * 0.15);  // match JAX f64->f32 cast

    const int s   = blockIdx.x * 16 + wid;
    const int far = g_fps[b * SS + s];
    const float4 cc = sp[far];

    int cnt = 0;
    for (int bp = 0; bp < NN; bp += 32) {
        int p = bp + lane;
        float4 q = sp[p];
        float d = dist3(q.x, q.y, q.z, cc.x, cc.y, cc.z);
        bool in = (d <= R2);
        unsigned m = __ballot_sync(0xffffffffu, in);
        int off = __popc(m & ((1u << lane) - 1u));
        if (in && cnt + off < NSMP) wbuf[wid][cnt + off] = p;
        cnt += __popc(m);
        if (cnt >= NSMP) { cnt = NSMP; break; }
    }
    __syncwarp();
    int v = (lane < cnt) ? wbuf[wid][lane] : wbuf[wid][0];
    g_gidx[((size_t)b * SS + s) * NSMP + lane] = v;
    atomicAdd(&g_cnt[b * NN + v], 1);
}

// ---------------- 4) h = points @ W + bvec  -------------------------------
// 128 threads/block, 32 rows/block, 2 channels per thread (w2 in registers).
__global__ __launch_bounds__(128, 2)
void hfull_kernel(const float* __restrict__ points) {
    __shared__ float psh[32 * CIN];  // 32 rows x 64 cols = 8 KB
    const int rowBase = blockIdx.x * 32;
    const int tid = threadIdx.x;

    {   // vectorized tile load: 512 float4, 128 threads -> 4 each
        const float4* src = (const float4*)(points + (size_t)rowBase * CIN);
        float4* dst = (float4*)psh;
#pragma unroll
        for (int i = 0; i < 4; ++i) dst[tid + 128 * i] = src[tid + 128 * i];
    }
    __syncthreads();

    const int c = tid * 2;  // channel pair (c, c+1)
    float2 w2[CIN];
#pragma unroll
    for (int k = 0; k < CIN; ++k)
        w2[k] = *(const float2*)&g_W[k * COUT + c];
    const float2 bv2 = *(const float2*)&g_bvec[c];

    for (int r0 = 0; r0 < 32; r0 += 4) {
        float a0x = bv2.x, a0y = bv2.y, a1x = bv2.x, a1y = bv2.y;
        float a2x = bv2.x, a2y = bv2.y, a3x = bv2.x, a3y = bv2.y;
        const float4* p0 = (const float4*)&psh[(r0 + 0) * CIN];
        const float4* p1 = (const float4*)&psh[(r0 + 1) * CIN];
        const float4* p2 = (const float4*)&psh[(r0 + 2) * CIN];
        const float4* p3 = (const float4*)&psh[(r0 + 3) * CIN];
#pragma unroll
        for (int k4 = 0; k4 < CIN / 4; ++k4) {
            float4 v0 = p0[k4], v1 = p1[k4], v2 = p2[k4], v3 = p3[k4];
            float2 u0 = w2[4 * k4], u1 = w2[4 * k4 + 1],
                   u2 = w2[4 * k4 + 2], u3 = w2[4 * k4 + 3];
            a0x = fmaf(v0.x, u0.x, a0x); a0y = fmaf(v0.x, u0.y, a0y);
            a0x = fmaf(v0.y, u1.x, a0x); a0y = fmaf(v0.y, u1.y, a0y);
            a0x = fmaf(v0.z, u2.x, a0x); a0y = fmaf(v0.z, u2.y, a0y);
            a0x = fmaf(v0.w, u3.x, a0x); a0y = fmaf(v0.w, u3.y, a0y);
            a1x = fmaf(v1.x, u0.x, a1x); a1y = fmaf(v1.x, u0.y, a1y);
            a1x = fmaf(v1.y, u1.x, a1x); a1y = fmaf(v1.y, u1.y, a1y);
            a1x = fmaf(v1.z, u2.x, a1x); a1y = fmaf(v1.z, u2.y, a1y);
            a1x = fmaf(v1.w, u3.x, a1x); a1y = fmaf(v1.w, u3.y, a1y);
            a2x = fmaf(v2.x, u0.x, a2x); a2y = fmaf(v2.x, u0.y, a2y);
            a2x = fmaf(v2.y, u1.x, a2x); a2y = fmaf(v2.y, u1.y, a2y);
            a2x = fmaf(v2.z, u2.x, a2x); a2y = fmaf(v2.z, u2.y, a2y);
            a2x = fmaf(v2.w, u3.x, a2x); a2y = fmaf(v2.w, u3.y, a2y);
            a3x = fmaf(v3.x, u0.x, a3x); a3y = fmaf(v3.x, u0.y, a3y);
            a3x = fmaf(v3.y, u1.x, a3x); a3y = fmaf(v3.y, u1.y, a3y);
            a3x = fmaf(v3.z, u2.x, a3x); a3y = fmaf(v3.z, u2.y, a3y);
            a3x = fmaf(v3.w, u3.x, a3x); a3y = fmaf(v3.w, u3.y, a3y);
        }
        *(float2*)&g_h[(size_t)(rowBase + r0 + 0) * COUT + c] = make_float2(a0x, a0y);
        *(float2*)&g_h[(size_t)(rowBase + r0 + 1) * COUT + c] = make_float2(a1x, a1y);
        *(float2*)&g_h[(size_t)(rowBase + r0 + 2) * COUT + c] = make_float2(a2x, a2y);
        *(float2*)&g_h[(size_t)(rowBase + r0 + 3) * COUT + c] = make_float2(a3x, a3y);
    }
}

// ---------------- 5) BN stats: count-weighted sum / sumsq per channel -----
__global__ __launch_bounds__(256)
void stats1_kernel() {
    const int c  = threadIdx.x;
    const int r0 = blockIdx.x * 128;
    float s = 0.f, q = 0.f;
    for (int r = r0; r < r0 + 128; ++r) {
        int w = g_cnt[r];
        if (w) {
            float v  = g_h[(size_t)r * COUT + c];
            float wv = (float)w * v;
            s += wv;
            q = fmaf(wv, v, q);
        }
    }
    g_part[((size_t)blockIdx.x * COUT + c) * 2 + 0] = s;
    g_part[((size_t)blockIdx.x * COUT + c) * 2 + 1] = q;
}

__global__ __launch_bounds__(256)
void stats2_kernel() {
    const int c = threadIdx.x;
    float s = 0.f, q = 0.f;
    for (int j = 0; j < 256; ++j) {
        s += g_part[((size_t)j * COUT + c) * 2 + 0];
        q += g_part[((size_t)j * COUT + c) * 2 + 1];
    }
    const float M = (float)(BB * SS * NSMP);  // 262144
    float mean = s / M;
    float var  = q / M - mean * mean;
    g_mean[c] = mean;
    g_istd[c] = 1.0f / sqrtf(var + 1e-5f);
}

// ---------------- 6) gather + max/min + BN-affine + relu ------------------
__global__ __launch_bounds__(128)
void final_kernel(const float* __restrict__ gamma,
                  const float* __restrict__ beta,
                  float* __restrict__ out) {
    const int sgl = blockIdx.x;      // 0..8191
    const int b   = sgl >> 10;
    const int t   = threadIdx.x;     // 0..127
    const int c   = t * 2;

    __shared__ int idxs[NSMP];
    if (t < NSMP) idxs[t] = g_gidx[(size_t)sgl * NSMP + t];
    __syncthreads();

    const float* hb = g_h + (size_t)b * NN * COUT + c;
    float vmaxx = -FLT_MAX, vmaxy = -FLT_MAX;
    float vminx =  FLT_MAX, vminy =  FLT_MAX;
#pragma unroll
    for (int n = 0; n < NSMP; ++n) {
        float2 v = *(const float2*)(hb + (size_t)idxs[n] * COUT);
        vmaxx = fmaxf(vmaxx, v.x); vmaxy = fmaxf(vmaxy, v.y);
        vminx = fminf(vminx, v.x); vminy = fminf(vminy, v.y);
    }
    float2 g = *(const float2*)&gamma[c];
    float2 be = *(const float2*)&beta[c];
    float2 is = *(const float2*)&g_istd[c];
    float2 mn = *(const float2*)&g_mean[c];
    float ax = g.x * is.x, ay = g.y * is.y;
    float bx = fmaf(-ax, mn.x, be.x), by = fmaf(-ay, mn.y, be.y);
    float vx = (ax >= 0.f) ? vmaxx : vminx;
    float vy = (ay >= 0.f) ? vmaxy : vminy;
    float2 o;
    o.x = fmaxf(0.f, fmaf(ax, vx, bx));
    o.y = fmaxf(0.f, fmaf(ay, vy, by));
    *(float2*)&out[(size_t)sgl * COUT + c] = o;
}

// ---------------- launch: forked-stream graph ------------------------------
// default stream: fps -> (wait wfuse) ballq -> (wait hfull) stats1/2 -> final
// side stream   : wfuse -> hfull            (overlaps fps)
extern "C" void kernel_launch(void* const* d_in, const int* in_sizes, int n_in,
                              void* d_out, int out_size) {
    const float* xyz    = (const float*)d_in[0];
    // d_in[1] = t, unused by the reference
    const float* points = (const float*)d_in[2];
    const float* W1     = (const float*)d_in[3];
    const float* b1     = (const float*)d_in[4];
    const float* Wc     = (const float*)d_in[5];
    const float* bc     = (const float*)d_in[6];
    const float* gamma  = (const float*)d_in[7];
    const float* beta   = (const float*)d_in[8];
    float* out = (float*)d_out;

    const size_t smemFPS = 3 * NN * sizeof(u64);     // 98304 B dynamic
    const size_t smemBQ  = NN * sizeof(float4);      // 65536 B dynamic

    cudaFuncSetAttribute(fps_kernel,
                         cudaFuncAttributeMaxDynamicSharedMemorySize, 131072);
    cudaFuncSetAttribute(ballq_kernel,
                         cudaFuncAttributeMaxDynamicSharedMemorySize, 98304);

    cudaStream_t s2;
    cudaStreamCreateWithFlags(&s2, cudaStreamNonBlocking);
    cudaEvent_t e0, ewf, ehf;
    cudaEventCreateWithFlags(&e0,  cudaEventDisableTiming);
    cudaEventCreateWithFlags(&ewf, cudaEventDisableTiming);
    cudaEventCreateWithFlags(&ehf, cudaEventDisableTiming);

    // fork side stream off the (possibly capturing) default stream
    cudaEventRecord(e0, 0);
    cudaStreamWaitEvent(s2, e0, 0);

    fps_kernel  <<<BB, 128, smemFPS, 0>>>(xyz);

    wfuse_kernel<<<64, 256, 0, s2>>>(W1, b1, Wc, bc);
    cudaEventRecord(ewf, s2);
    hfull_kernel<<<(BB * NN) / 32, 128, 0, s2>>>(points);
    cudaEventRecord(ehf, s2);

    cudaStreamWaitEvent(0, ewf, 0);   // ballq needs g_cnt zeroed (wfuse)
    ballq_kernel<<<dim3(SS / 16, BB), 512, smemBQ, 0>>>(xyz);

    cudaStreamWaitEvent(0, ehf, 0);   // join side stream: stats need g_h
    stats1_kernel<<<256, 256, 0, 0>>>();
    stats2_kernel<<<1, 256, 0, 0>>>();
    final_kernel<<<BB * SS, 128, 0, 0>>>(gamma, beta, out);
    // handles intentionally leaked: capture may still be in progress and
    // kernel_launch is invoked only a few times outside graph replay.
}